// round 1
// baseline (speedup 1.0000x reference)
#include <cuda_runtime.h>
#include <cstdint>

// ---------------- problem constants ----------------
#define K_TOTAL 33154      // MAXOUT
#define SEG1    16641      // MAX_ST   (st segment end)
#define SEG2    16770      // SEG1+129 (at segment end)
#define ST1_LEN 16384
#define AT_LEN  129
#define NBATCH  1024
#define NHID    512
#define NOUT    129

// ---------------- GEMM1 tiling ----------------
#define BM 64
#define BN 128
#define BK 16
#define SPLITK 8
#define CHUNK ((K_TOTAL + SPLITK - 1) / SPLITK)   // 4145
#define MT (NBATCH / BM)    // 16
#define NT (NHID  / BN)     // 4

// Split-K partial sums: 8 * 1024 * 512 * 4B = 16 MB device scratch.
__device__ float g_hpart[SPLITK][NBATCH][NHID];

// ---------------- packed f32x2 helpers (Blackwell FFMA2) ----------------
__device__ __forceinline__ unsigned long long pack2(float x, float y) {
    unsigned long long r;
    asm("mov.b64 %0, {%1, %2};" : "=l"(r) : "f"(x), "f"(y));
    return r;
}
__device__ __forceinline__ void fma2(unsigned long long& c,
                                     unsigned long long a,
                                     unsigned long long b) {
    asm("fma.rn.f32x2 %0, %1, %2, %0;" : "+l"(c) : "l"(a), "l"(b));
}
__device__ __forceinline__ float2 unpack2(unsigned long long v) {
    float2 r;
    asm("mov.b64 {%0, %1}, %2;" : "=f"(r.x), "=f"(r.y) : "l"(v));
    return r;
}

// x[b, k] over the concatenated feature axis (st | at | st1)
__device__ __forceinline__ float load_x(const float* __restrict__ st,
                                        const float* __restrict__ at,
                                        const float* __restrict__ st1,
                                        int b, int k) {
    if (k < SEG1)  return st [b * SEG1    + k];
    if (k < SEG2)  return at [b * AT_LEN  + (k - SEG1)];
    return st1[b * ST1_LEN + (k - SEG2)];
}

// ======================================================================
// GEMM1: h_part[split][b][n] = sum_{k in split-chunk} x[b,k] * W1[k,n]
// CTA tile: 64 (M) x 128 (N) x 16 (K). 256 threads; each thread 4x8 outputs
// held as 16 packed f32x2 accumulators.
// ======================================================================
__global__ void __launch_bounds__(256, 2)
gemm1_kernel(const float* __restrict__ st,
             const float* __restrict__ at,
             const float* __restrict__ st1,
             const float* __restrict__ W1)
{
    // As stored transposed [BK][BM+4] (pad 4 floats: keeps float4 alignment,
    // reduces store bank conflicts). Bs [BK][BN], 16B aligned for packed reads.
    __shared__ __align__(16) float As[BK * (BM + 4)];
    __shared__ __align__(16) float Bs[BK * BN];

    const int tid = threadIdx.x;          // 0..255
    const int tx  = tid & 15;             // N direction, 16 threads * 8 cols
    const int ty  = tid >> 4;             // M direction, 16 threads * 4 rows

    const int tile = blockIdx.x;          // 0..63
    const int mt = tile & (MT - 1);       // 0..15
    const int nt = tile >> 4;             // 0..3
    const int split = blockIdx.y;

    const int b0 = mt * BM;
    const int n0 = nt * BN;
    const int kstart = split * CHUNK;
    const int kend   = min(kstart + CHUNK, K_TOTAL);

    unsigned long long c[4][4];
    #pragma unroll
    for (int i = 0; i < 4; i++)
        #pragma unroll
        for (int j = 0; j < 4; j++) c[i][j] = 0ULL;   // {0.f, 0.f}

    for (int k0 = kstart; k0 < kend; k0 += BK) {
        // ---- load A tile: 64 rows x 16 cols, coalesced along k ----
        #pragma unroll
        for (int i = 0; i < 4; i++) {
            int lin = tid + i * 256;          // 0..1023
            int kk  = lin & (BK - 1);
            int m   = lin >> 4;
            int k   = k0 + kk;
            float v = (k < kend) ? load_x(st, at, st1, b0 + m, k) : 0.0f;
            As[kk * (BM + 4) + m] = v;
        }
        // ---- load B tile: 16 rows x 128 cols via float4, fully coalesced ----
        #pragma unroll
        for (int i = 0; i < 2; i++) {
            int lin4 = tid + i * 256;         // quad index 0..511
            int kk   = lin4 >> 5;             // /32 quads per row
            int c4   = (lin4 & 31) << 2;      // column *4
            int k    = k0 + kk;
            float4 v = (k < kend)
                     ? *reinterpret_cast<const float4*>(W1 + (size_t)k * NHID + n0 + c4)
                     : make_float4(0.f, 0.f, 0.f, 0.f);
            *reinterpret_cast<float4*>(&Bs[kk * BN + c4]) = v;
        }
        __syncthreads();

        #pragma unroll
        for (int kk = 0; kk < BK; kk++) {
            // A: 4 scalars for this thread's rows
            float4 av = *reinterpret_cast<const float4*>(&As[kk * (BM + 4) + ty * 4]);
            unsigned long long a2[4];
            a2[0] = pack2(av.x, av.x);
            a2[1] = pack2(av.y, av.y);
            a2[2] = pack2(av.z, av.z);
            a2[3] = pack2(av.w, av.w);
            // B: 8 floats = 4 packed pairs, loaded directly as b64 pairs
            const ulonglong2* bsrc =
                reinterpret_cast<const ulonglong2*>(&Bs[kk * BN + tx * 8]);
            ulonglong2 bv0 = bsrc[0];
            ulonglong2 bv1 = bsrc[1];
            unsigned long long b2v[4] = { bv0.x, bv0.y, bv1.x, bv1.y };

            #pragma unroll
            for (int i = 0; i < 4; i++)
                #pragma unroll
                for (int j = 0; j < 4; j++)
                    fma2(c[i][j], a2[i], b2v[j]);
        }
        __syncthreads();
    }

    // ---- epilogue: write 4x8 tile to split-K partial buffer ----
    const int row0 = b0 + ty * 4;
    const int col0 = n0 + tx * 8;
    #pragma unroll
    for (int i = 0; i < 4; i++) {
        float2 p0 = unpack2(c[i][0]);
        float2 p1 = unpack2(c[i][1]);
        float2 p2 = unpack2(c[i][2]);
        float2 p3 = unpack2(c[i][3]);
        float4 o0 = make_float4(p0.x, p0.y, p1.x, p1.y);
        float4 o1 = make_float4(p2.x, p2.y, p3.x, p3.y);
        float* dst = &g_hpart[split][row0 + i][col0];
        *reinterpret_cast<float4*>(dst)     = o0;
        *reinterpret_cast<float4*>(dst + 4) = o1;
    }
}

// ======================================================================
// Stage 2: reduce split-K partials, +b1, ReLU, then h @ W2 + b2.
// One CTA per batch row. W2 is [512, 129] row-major -> W2[n*129 + j].
// ======================================================================
__global__ void __launch_bounds__(256)
mlp2_kernel(const float* __restrict__ b1,
            const float* __restrict__ W2,
            const float* __restrict__ b2,
            float* __restrict__ out)
{
    __shared__ float hs[NHID];
    const int b   = blockIdx.x;
    const int tid = threadIdx.x;

    #pragma unroll
    for (int n = tid; n < NHID; n += 256) {
        float s = 0.0f;
        #pragma unroll
        for (int sp = 0; sp < SPLITK; sp++) s += g_hpart[sp][b][n];
        s += b1[n];
        hs[n] = fmaxf(s, 0.0f);
    }
    __syncthreads();

    if (tid < NOUT) {
        float a0 = 0.f, a1 = 0.f, a2 = 0.f, a3 = 0.f;
        #pragma unroll 8
        for (int n = 0; n < NHID; n += 4) {
            a0 = fmaf(hs[n + 0], W2[(n + 0) * NOUT + tid], a0);
            a1 = fmaf(hs[n + 1], W2[(n + 1) * NOUT + tid], a1);
            a2 = fmaf(hs[n + 2], W2[(n + 2) * NOUT + tid], a2);
            a3 = fmaf(hs[n + 3], W2[(n + 3) * NOUT + tid], a3);
        }
        out[b * NOUT + tid] = (a0 + a1) + (a2 + a3) + b2[tid];
    }
}

// ======================================================================
// kernel_launch — graph-capturable, allocation-free.
// Input order (metadata): st, at, st1, W1, b1, W2, b2. Output: float32.
// ======================================================================
extern "C" void kernel_launch(void* const* d_in, const int* in_sizes, int n_in,
                              void* d_out, int out_size)
{
    const float* st  = (const float*)d_in[0];
    const float* at  = (const float*)d_in[1];
    const float* st1 = (const float*)d_in[2];
    const float* W1  = (const float*)d_in[3];
    const float* b1  = (const float*)d_in[4];
    const float* W2  = (const float*)d_in[5];
    const float* b2  = (const float*)d_in[6];
    float* out = (float*)d_out;

    dim3 grid1(MT * NT, SPLITK);   // 64 tiles x 8 K-splits = 512 CTAs
    gemm1_kernel<<<grid1, 256>>>(st, at, st1, W1);
    mlp2_kernel<<<NBATCH, 256>>>(b1, W2, b2, out);
}

// round 2
// speedup vs baseline: 1.8839x; 1.8839x over previous
#include <cuda_runtime.h>
#include <cstdint>

// ---------------- problem constants ----------------
#define K_TOTAL 33154      // MAXOUT
#define SEG1    16641      // MAX_ST   (st segment end)
#define SEG2    16770      // SEG1+129 (at segment end)
#define ST1_LEN 16384
#define AT_LEN  129
#define NBATCH  1024
#define NHID    512
#define NOUT    129

// ---------------- GEMM1 tiling ----------------
#define BM 64
#define BN 128
#define BK 16
#define SPLITK 8
#define CHUNK ((K_TOTAL + SPLITK - 1) / SPLITK)   // 4145
#define MT (NBATCH / BM)    // 16
#define NT (NHID  / BN)     // 4
#define APAD 4
#define ASTRIDE (BM + APAD) // 68

// Split-K partial sums: 8 * 1024 * 512 * 4B = 16 MB device scratch.
__device__ float g_hpart[SPLITK][NBATCH][NHID];

// ---------------- packed f32x2 helpers (Blackwell FFMA2) ----------------
__device__ __forceinline__ unsigned long long pack2(float x, float y) {
    unsigned long long r;
    asm("mov.b64 %0, {%1, %2};" : "=l"(r) : "f"(x), "f"(y));
    return r;
}
__device__ __forceinline__ void fma2(unsigned long long& c,
                                     unsigned long long a,
                                     unsigned long long b) {
    asm("fma.rn.f32x2 %0, %1, %2, %0;" : "+l"(c) : "l"(a), "l"(b));
}
__device__ __forceinline__ float2 unpack2(unsigned long long v) {
    float2 r;
    asm("mov.b64 {%0, %1}, %2;" : "=f"(r.x), "=f"(r.y) : "l"(v));
    return r;
}

// x[b, k] over the concatenated feature axis (st | at | st1)
__device__ __forceinline__ float load_x(const float* __restrict__ st,
                                        const float* __restrict__ at,
                                        const float* __restrict__ st1,
                                        int b, int k) {
    if (k < SEG1)  return st [b * SEG1    + k];
    if (k < SEG2)  return at [b * AT_LEN  + (k - SEG1)];
    return st1[b * ST1_LEN + (k - SEG2)];
}

// ======================================================================
// GEMM1: h_part[split][b][n] = sum_{k in split-chunk} x[b,k] * W1[k,n]
// CTA tile: 64 (M) x 128 (N) x 16 (K). 256 threads; each thread owns a
// 4-row x (4+4)-col output patch: columns [tx*4, tx*4+4) and
// [64+tx*4, 64+tx*4+4). This makes the per-kk B reads two conflict-free
// LDS.128 (consecutive threads -> consecutive 16B).
// Gmem->smem stage is register double-buffered to overlap load latency
// with the FMA loop.
// ======================================================================
__global__ void __launch_bounds__(256, 2)
gemm1_kernel(const float* __restrict__ st,
             const float* __restrict__ at,
             const float* __restrict__ st1,
             const float* __restrict__ W1)
{
    __shared__ __align__(16) float As[BK * ASTRIDE];
    __shared__ __align__(16) float Bs[BK * BN];

    const int tid = threadIdx.x;          // 0..255
    const int tx  = tid & 15;             // N direction
    const int ty  = tid >> 4;             // M direction

    const int tile = blockIdx.x;          // 0..63
    const int mt = tile & (MT - 1);       // 0..15
    const int nt = tile >> 4;             // 0..3
    const int split = blockIdx.y;

    const int b0 = mt * BM;
    const int n0 = nt * BN;
    const int kstart = split * CHUNK;
    const int kend   = min(kstart + CHUNK, K_TOTAL);

    // ---- per-thread gmem->smem assignments (fixed across iterations) ----
    // A: 4 elements, lin = tid + i*256 over 64x16 tile (k fastest)
    const int a_kk[4] = { tid & (BK-1), tid & (BK-1), tid & (BK-1), tid & (BK-1) };
    const int a_m [4] = { tid >> 4, (tid + 256) >> 4, (tid + 512) >> 4, (tid + 768) >> 4 };
    // B: 2 float4, quad index lin4 = tid + i*256 over 16x(128/4)
    const int b_kk[2] = { tid >> 5, (tid + 256) >> 5 };
    const int b_c4[2] = { (tid & 31) << 2, (tid & 31) << 2 };

    unsigned long long c[4][4];
    #pragma unroll
    for (int i = 0; i < 4; i++)
        #pragma unroll
        for (int j = 0; j < 4; j++) c[i][j] = 0ULL;

    // ---- prologue: load first tile into registers ----
    float  aR[4];
    float4 bR[2];
    {
        #pragma unroll
        for (int i = 0; i < 4; i++) {
            int k = kstart + a_kk[i];
            aR[i] = (k < kend) ? load_x(st, at, st1, b0 + a_m[i], k) : 0.0f;
        }
        #pragma unroll
        for (int i = 0; i < 2; i++) {
            int k = kstart + b_kk[i];
            bR[i] = (k < kend)
                  ? *reinterpret_cast<const float4*>(W1 + (size_t)k * NHID + n0 + b_c4[i])
                  : make_float4(0.f, 0.f, 0.f, 0.f);
        }
    }

    for (int k0 = kstart; k0 < kend; k0 += BK) {
        // ---- commit current registers to smem ----
        #pragma unroll
        for (int i = 0; i < 4; i++)
            As[a_kk[i] * ASTRIDE + a_m[i]] = aR[i];
        #pragma unroll
        for (int i = 0; i < 2; i++)
            *reinterpret_cast<float4*>(&Bs[b_kk[i] * BN + b_c4[i]]) = bR[i];
        __syncthreads();

        // ---- preload next tile into registers (overlaps with FMA loop) ----
        const int kn = k0 + BK;
        if (kn < kend) {
            #pragma unroll
            for (int i = 0; i < 4; i++) {
                int k = kn + a_kk[i];
                aR[i] = (k < kend) ? load_x(st, at, st1, b0 + a_m[i], k) : 0.0f;
            }
            #pragma unroll
            for (int i = 0; i < 2; i++) {
                int k = kn + b_kk[i];
                bR[i] = (k < kend)
                      ? *reinterpret_cast<const float4*>(W1 + (size_t)k * NHID + n0 + b_c4[i])
                      : make_float4(0.f, 0.f, 0.f, 0.f);
            }
        }

        // ---- FMA mainloop over BK ----
        #pragma unroll
        for (int kk = 0; kk < BK; kk++) {
            float4 av = *reinterpret_cast<const float4*>(&As[kk * ASTRIDE + ty * 4]);
            unsigned long long a2[4];
            a2[0] = pack2(av.x, av.x);
            a2[1] = pack2(av.y, av.y);
            a2[2] = pack2(av.z, av.z);
            a2[3] = pack2(av.w, av.w);
            // conflict-free: consecutive tx -> consecutive 16B
            ulonglong2 bv0 = *reinterpret_cast<const ulonglong2*>(&Bs[kk * BN + tx * 4]);
            ulonglong2 bv1 = *reinterpret_cast<const ulonglong2*>(&Bs[kk * BN + 64 + tx * 4]);
            unsigned long long b2v[4] = { bv0.x, bv0.y, bv1.x, bv1.y };

            #pragma unroll
            for (int i = 0; i < 4; i++)
                #pragma unroll
                for (int j = 0; j < 4; j++)
                    fma2(c[i][j], a2[i], b2v[j]);
        }
        __syncthreads();
    }

    // ---- epilogue: write 4 rows x two float4 column groups ----
    const int row0  = b0 + ty * 4;
    const int col0a = n0 + tx * 4;
    const int col0b = n0 + 64 + tx * 4;
    #pragma unroll
    for (int i = 0; i < 4; i++) {
        float2 p0 = unpack2(c[i][0]);
        float2 p1 = unpack2(c[i][1]);
        float2 p2 = unpack2(c[i][2]);
        float2 p3 = unpack2(c[i][3]);
        float* base = &g_hpart[split][row0 + i][0];
        *reinterpret_cast<float4*>(base + col0a) = make_float4(p0.x, p0.y, p1.x, p1.y);
        *reinterpret_cast<float4*>(base + col0b) = make_float4(p2.x, p2.y, p3.x, p3.y);
    }
}

// ======================================================================
// Stage 2: reduce split-K partials, +b1, ReLU, then h @ W2 + b2.
// One CTA per batch row. W2 is [512, 129] row-major -> W2[n*129 + j].
// ======================================================================
__global__ void __launch_bounds__(256)
mlp2_kernel(const float* __restrict__ b1,
            const float* __restrict__ W2,
            const float* __restrict__ b2,
            float* __restrict__ out)
{
    __shared__ float hs[NHID];
    const int b   = blockIdx.x;
    const int tid = threadIdx.x;

    #pragma unroll
    for (int n = tid; n < NHID; n += 256) {
        float s = 0.0f;
        #pragma unroll
        for (int sp = 0; sp < SPLITK; sp++) s += g_hpart[sp][b][n];
        s += b1[n];
        hs[n] = fmaxf(s, 0.0f);
    }
    __syncthreads();

    if (tid < NOUT) {
        float a0 = 0.f, a1 = 0.f, a2 = 0.f, a3 = 0.f;
        #pragma unroll 8
        for (int n = 0; n < NHID; n += 4) {
            a0 = fmaf(hs[n + 0], W2[(n + 0) * NOUT + tid], a0);
            a1 = fmaf(hs[n + 1], W2[(n + 1) * NOUT + tid], a1);
            a2 = fmaf(hs[n + 2], W2[(n + 2) * NOUT + tid], a2);
            a3 = fmaf(hs[n + 3], W2[(n + 3) * NOUT + tid], a3);
        }
        out[b * NOUT + tid] = (a0 + a1) + (a2 + a3) + b2[tid];
    }
}

// ======================================================================
// kernel_launch — graph-capturable, allocation-free.
// Input order (metadata): st, at, st1, W1, b1, W2, b2. Output: float32.
// ======================================================================
extern "C" void kernel_launch(void* const* d_in, const int* in_sizes, int n_in,
                              void* d_out, int out_size)
{
    const float* st  = (const float*)d_in[0];
    const float* at  = (const float*)d_in[1];
    const float* st1 = (const float*)d_in[2];
    const float* W1  = (const float*)d_in[3];
    const float* b1  = (const float*)d_in[4];
    const float* W2  = (const float*)d_in[5];
    const float* b2  = (const float*)d_in[6];
    float* out = (float*)d_out;

    dim3 grid1(MT * NT, SPLITK);   // 64 tiles x 8 K-splits = 512 CTAs
    gemm1_kernel<<<grid1, 256>>>(st, at, st1, W1);
    mlp2_kernel<<<NBATCH, 256>>>(b1, W2, b2, out);
}

// round 6
// speedup vs baseline: 4.5584x; 2.4196x over previous
#include <cuda_runtime.h>
#include <cuda_bf16.h>
#include <cstdint>

// ---------------- problem constants ----------------
#define K_TOTAL 33154
#define SEG1    16641
#define SEG2    16770
#define AT_LEN  129
#define ST1_LEN 16384
#define NBATCH  1024
#define NHID    512
#define NOUT    129

// ---------------- padded / tiling constants ----------------
#define KPAD    33280            // 8 * 4160 = 65*64*8
#define SPLITK  8
#define KSPLIT  (KPAD / SPLITK)  // 4160
#define CK      64               // K per smem chunk (128B bf16 rows)
#define NCHUNK  (KSPLIT / CK)    // 65
#define TM      128
#define TN      128
#define MT      (NBATCH / TM)    // 8
#define NT      (NHID  / TN)     // 4

// ---------------- device scratch ----------------
__device__ float g_hpart[SPLITK][NBATCH][NHID];                 // 16 MB
__device__ __align__(128) __nv_bfloat16 g_xh[NBATCH][KPAD];     // 68 MB
__device__ __align__(128) __nv_bfloat16 g_xl[NBATCH][KPAD];     // 68 MB
__device__ __align__(128) __nv_bfloat16 g_wh[NHID][KPAD];       // 34 MB
__device__ __align__(128) __nv_bfloat16 g_wl[NHID][KPAD];       // 34 MB

// ---------------- helpers ----------------
__device__ __forceinline__ uint32_t smem_u32(const void* p) {
    uint32_t a;
    asm("{ .reg .u64 t; cvta.to.shared.u64 t, %1; cvt.u32.u64 %0, t; }"
        : "=r"(a) : "l"(p));
    return a;
}
#define SWZ128(o) (((uint32_t)(o)) ^ ((((uint32_t)(o)) >> 3) & 0x70u))

__device__ __forceinline__ void cp_async16(uint32_t dst, const void* src) {
    asm volatile("cp.async.cg.shared.global [%0], [%1], 16;" :: "r"(dst), "l"(src) : "memory");
}
#define CP_COMMIT() asm volatile("cp.async.commit_group;" ::: "memory")
#define CP_WAIT1()  asm volatile("cp.async.wait_group 1;" ::: "memory")
#define CP_WAIT0()  asm volatile("cp.async.wait_group 0;" ::: "memory")

#define LDM_X4(r0, r1, r2, r3, a) \
    asm volatile("ldmatrix.sync.aligned.m8n8.x4.shared.b16 {%0,%1,%2,%3}, [%4];" \
                 : "=r"(r0), "=r"(r1), "=r"(r2), "=r"(r3) : "r"(a))

__device__ __forceinline__ void mma_bf16(float* c, const uint32_t* a, const uint32_t* b) {
    asm volatile(
        "mma.sync.aligned.m16n8k16.row.col.f32.bf16.bf16.f32 "
        "{%0,%1,%2,%3}, {%4,%5,%6,%7}, {%8,%9}, {%0,%1,%2,%3};"
        : "+f"(c[0]), "+f"(c[1]), "+f"(c[2]), "+f"(c[3])
        : "r"(a[0]), "r"(a[1]), "r"(a[2]), "r"(a[3]), "r"(b[0]), "r"(b[1]));
}

// ---------------- x concat access ----------------
__device__ __forceinline__ float load_x(const float* __restrict__ st,
                                        const float* __restrict__ at,
                                        const float* __restrict__ st1,
                                        int b, int k) {
    if (k < SEG1)  return st [b * SEG1    + k];
    if (k < SEG2)  return at [b * AT_LEN  + (k - SEG1)];
    return st1[b * ST1_LEN + (k - SEG2)];
}

// ======================================================================
// convert_x: x -> (xh, xl) bf16 split, zero-padded to KPAD.
// ======================================================================
__global__ void __launch_bounds__(128)
convert_x_kernel(const float* __restrict__ st, const float* __restrict__ at,
                 const float* __restrict__ st1)
{
    const int m = blockIdx.y;
    const int k = (blockIdx.x * 128 + threadIdx.x) * 2;
    float v0 = (k     < K_TOTAL) ? load_x(st, at, st1, m, k)     : 0.0f;
    float v1 = (k + 1 < K_TOTAL) ? load_x(st, at, st1, m, k + 1) : 0.0f;
    __nv_bfloat16 h0 = __float2bfloat16(v0);
    __nv_bfloat16 h1 = __float2bfloat16(v1);
    __nv_bfloat16 l0 = __float2bfloat16(v0 - __bfloat162float(h0));
    __nv_bfloat16 l1 = __float2bfloat16(v1 - __bfloat162float(h1));
    *reinterpret_cast<__nv_bfloat162*>(&g_xh[m][k]) = __nv_bfloat162(h0, h1);
    *reinterpret_cast<__nv_bfloat162*>(&g_xl[m][k]) = __nv_bfloat162(l0, l1);
}

// ======================================================================
// convert_w: W1 [K][512] fp32 -> transposed (wh, wl) [512][KPAD] bf16.
// ======================================================================
__global__ void __launch_bounds__(256)
convert_w_kernel(const float* __restrict__ W1)
{
    __shared__ float tile[32][33];
    const int k0 = blockIdx.x * 32;
    const int n0 = blockIdx.y * 32;
    const int tx = threadIdx.x, ty = threadIdx.y;

    #pragma unroll
    for (int i = 0; i < 4; i++) {
        int k = k0 + ty + i * 8;
        tile[ty + i * 8][tx] = (k < K_TOTAL) ? W1[(size_t)k * NHID + n0 + tx] : 0.0f;
    }
    __syncthreads();
    #pragma unroll
    for (int i = 0; i < 4; i++) {
        int n = n0 + ty + i * 8;
        float v = tile[tx][ty + i * 8];
        __nv_bfloat16 h = __float2bfloat16(v);
        __nv_bfloat16 l = __float2bfloat16(v - __bfloat162float(h));
        g_wh[n][k0 + tx] = h;
        g_wl[n][k0 + tx] = l;
    }
}

// ======================================================================
// GEMM1 via warp-level mma.sync (bf16, 3-term split accumulated in fp32).
// CTA tile 128x128, split-K over blockIdx.z. Per K-chunk of 64 we stage
// xh, xl, wh, wl tiles (4 x 16KB, SW128 swizzle, double buffered = 128KB)
// and run the 3 pass-MMAs from the same residency.
// 8 warps: 2 (M) x 4 (N); warp tile 64x32 -> 4 m16 tiles x 4 n8 tiles.
// ======================================================================
__global__ void __launch_bounds__(256, 1)
gemm_mma_kernel()
{
    extern __shared__ char dyn_smem[];
    const uint32_t base = (smem_u32(dyn_smem) + 1023u) & ~1023u;

    const int tid  = threadIdx.x;
    const int wid  = tid >> 5;
    const int lane = tid & 31;

    const int m0 = blockIdx.x * TM;
    const int n0 = blockIdx.y * TN;
    const int split = blockIdx.z;
    const int kbase = split * KSPLIT;

    const int mwarp = (wid >> 2) * 64;   // 0 or 64
    const int nwarp = (wid & 3) * 32;    // 0,32,64,96

    // ldmatrix per-lane address components
    const int a_row = lane & 15;                    // m within 16
    const int a_col = (lane >> 4) * 16;             // k-byte within 32
    const int b_row = (lane & 7) + ((lane >> 4) << 3);  // n within 16
    const int b_col = ((lane >> 3) & 1) * 16;       // k-byte within 32

    float c[4][4][4];
    #pragma unroll
    for (int i = 0; i < 4; i++)
        #pragma unroll
        for (int j = 0; j < 4; j++)
            #pragma unroll
            for (int e = 0; e < 4; e++) c[i][j][e] = 0.0f;

    // per-chunk tile loads: 4 tiles of 128 rows x 8 quads (16B each)
    auto issue_loads = [&](int ch) {
        const int k0 = kbase + ch * CK;
        const uint32_t buf = (ch & 1) ? 65536u : 0u;
        const __nv_bfloat16* srcs[4] = {
            &g_xh[m0][k0], &g_xl[m0][k0], &g_wh[n0][k0], &g_wl[n0][k0]
        };
        #pragma unroll
        for (int s = 0; s < 4; s++) {
            const uint32_t dst = base + buf + s * 16384u;
            const __nv_bfloat16* sp = srcs[s];
            #pragma unroll
            for (int t = 0; t < 4; t++) {
                int q = tid + t * 256;
                int row = q >> 3, qc = q & 7;
                cp_async16(dst + SWZ128(row * 128 + qc * 16),
                           sp + (size_t)row * KPAD + qc * 8);
            }
        }
        CP_COMMIT();
    };

    issue_loads(0);

    for (int i = 0; i < NCHUNK; i++) {
        if (i + 1 < NCHUNK) { issue_loads(i + 1); CP_WAIT1(); }
        else                { CP_WAIT0(); }
        __syncthreads();

        const uint32_t buf = base + ((i & 1) ? 65536u : 0u);
        const uint32_t Ah = buf, Al = buf + 16384u;
        const uint32_t Bh = buf + 32768u, Bl = buf + 49152u;

        #pragma unroll
        for (int kk = 0; kk < 4; kk++) {
            uint32_t ah[4][4], al[4][4], bh[4][2], bl[4][2];
            #pragma unroll
            for (int t = 0; t < 4; t++) {
                uint32_t offA = SWZ128((mwarp + t * 16 + a_row) * 128 + kk * 32 + a_col);
                LDM_X4(ah[t][0], ah[t][1], ah[t][2], ah[t][3], Ah + offA);
                LDM_X4(al[t][0], al[t][1], al[t][2], al[t][3], Al + offA);
            }
            #pragma unroll
            for (int t = 0; t < 2; t++) {
                uint32_t offB = SWZ128((nwarp + t * 16 + b_row) * 128 + kk * 32 + b_col);
                LDM_X4(bh[2*t][0], bh[2*t][1], bh[2*t+1][0], bh[2*t+1][1], Bh + offB);
                LDM_X4(bl[2*t][0], bl[2*t][1], bl[2*t+1][0], bl[2*t+1][1], Bl + offB);
            }
            #pragma unroll
            for (int mi = 0; mi < 4; mi++)
                #pragma unroll
                for (int nj = 0; nj < 4; nj++) {
                    mma_bf16(c[mi][nj], ah[mi], bh[nj]);   // xh * wh
                    mma_bf16(c[mi][nj], ah[mi], bl[nj]);   // xh * wl
                    mma_bf16(c[mi][nj], al[mi], bh[nj]);   // xl * wh
                }
        }
        __syncthreads();
    }

    // epilogue: c frag layout m16n8 -> rows (lane/4, +8), cols 2*(lane%4)
    const int er  = lane >> 2;
    const int ec  = (lane & 3) * 2;
    #pragma unroll
    for (int mi = 0; mi < 4; mi++) {
        const int row = m0 + mwarp + mi * 16 + er;
        #pragma unroll
        for (int nj = 0; nj < 4; nj++) {
            const int col = n0 + nwarp + nj * 8 + ec;
            *reinterpret_cast<float2*>(&g_hpart[split][row][col]) =
                make_float2(c[mi][nj][0], c[mi][nj][1]);
            *reinterpret_cast<float2*>(&g_hpart[split][row + 8][col]) =
                make_float2(c[mi][nj][2], c[mi][nj][3]);
        }
    }
}

// ======================================================================
// Stage 2: reduce split-K partials, +b1, ReLU, then h @ W2 + b2.
// ======================================================================
__global__ void __launch_bounds__(256)
mlp2_kernel(const float* __restrict__ b1,
            const float* __restrict__ W2,
            const float* __restrict__ b2,
            float* __restrict__ out)
{
    __shared__ float hs[NHID];
    const int b   = blockIdx.x;
    const int tid = threadIdx.x;

    #pragma unroll
    for (int n = tid; n < NHID; n += 256) {
        float s = 0.0f;
        #pragma unroll
        for (int sp = 0; sp < SPLITK; sp++) s += g_hpart[sp][b][n];
        s += b1[n];
        hs[n] = fmaxf(s, 0.0f);
    }
    __syncthreads();

    if (tid < NOUT) {
        float a0 = 0.f, a1 = 0.f, a2 = 0.f, a3 = 0.f;
        #pragma unroll 8
        for (int n = 0; n < NHID; n += 4) {
            a0 = fmaf(hs[n + 0], W2[(n + 0) * NOUT + tid], a0);
            a1 = fmaf(hs[n + 1], W2[(n + 1) * NOUT + tid], a1);
            a2 = fmaf(hs[n + 2], W2[(n + 2) * NOUT + tid], a2);
            a3 = fmaf(hs[n + 3], W2[(n + 3) * NOUT + tid], a3);
        }
        out[b * NOUT + tid] = (a0 + a1) + (a2 + a3) + b2[tid];
    }
}

// ======================================================================
// kernel_launch — graph-capturable, allocation-free.
// Input order (metadata): st, at, st1, W1, b1, W2, b2. Output: float32.
// ======================================================================
extern "C" void kernel_launch(void* const* d_in, const int* in_sizes, int n_in,
                              void* d_out, int out_size)
{
    const float* st  = (const float*)d_in[0];
    const float* at  = (const float*)d_in[1];
    const float* st1 = (const float*)d_in[2];
    const float* W1  = (const float*)d_in[3];
    const float* b1  = (const float*)d_in[4];
    const float* W2  = (const float*)d_in[5];
    const float* b2  = (const float*)d_in[6];
    float* out = (float*)d_out;

    dim3 gx(KPAD / 256, NBATCH);
    convert_x_kernel<<<gx, 128>>>(st, at, st1);

    dim3 gw(KPAD / 32, NHID / 32);
    convert_w_kernel<<<gw, dim3(32, 8)>>>(W1);

    const int dyn_smem = 131072 + 1024;   // 2 x 64KB buffers + align slack
    cudaFuncSetAttribute(gemm_mma_kernel,
                         cudaFuncAttributeMaxDynamicSharedMemorySize, dyn_smem);
    dim3 gg(MT, NT, SPLITK);              // 8 x 4 x 8 = 256 CTAs
    gemm_mma_kernel<<<gg, 256, dyn_smem>>>();

    mlp2_kernel<<<NBATCH, 256>>>(b1, W2, b2, out);
}